// round 1
// baseline (speedup 1.0000x reference)
#include <cuda_runtime.h>
#include <cuda_bf16.h>
#include <math.h>

// Problem constants
#define Bb 2
#define Ss 4096
#define Hh 1024
#define NKH 8
#define NVH 16
#define DK 64
#define DV 64
#define KEY_DIM 512          // NKH*DK
#define VAL_DIM 1024         // NVH*DV
#define CONV_DIM 2048        // 2*KEY_DIM+VAL_DIM
#define KSZ 4
#define MROWS (Bb*Ss)        // 8192

// ------------------------- scratch (static device memory) -------------------
__device__ float g_mixed[(size_t)Bb*Ss*CONV_DIM];   // qkv pre-conv
__device__ float g_conv [(size_t)Bb*Ss*CONV_DIM];   // after conv+silu
__device__ float g_z    [(size_t)Bb*Ss*VAL_DIM];
__device__ float g_g    [(size_t)Bb*Ss*NVH];
__device__ float g_beta [(size_t)Bb*Ss*NVH];
__device__ float g_o    [(size_t)Bb*Ss*VAL_DIM];
__device__ float g_h    [(size_t)Bb*Ss*VAL_DIM];

// ------------------------- generic SGEMM: C = A * B^T -----------------------
// A: [M,K] row-major, B: [N,K] row-major, C: [M,N]. M%128==0, N%128==0, K%8==0.
#define BM 128
#define BN 128
#define BKK 8

__global__ __launch_bounds__(256) void sgemm_tn(const float* __restrict__ A,
                                                const float* __restrict__ B,
                                                float* __restrict__ C,
                                                int M, int N, int K) {
    __shared__ float As[BKK][BM];
    __shared__ float Bs[BKK][BN];

    const int tid  = threadIdx.x;
    const int brow = blockIdx.y * BM;
    const int bcol = blockIdx.x * BN;

    const int lrow = tid >> 1;          // 0..127
    const int lk4  = (tid & 1) * 4;     // 0 or 4
    const float* Aptr = A + (size_t)(brow + lrow) * K + lk4;
    const float* Bptr = B + (size_t)(bcol + lrow) * K + lk4;

    const int ty = tid >> 4;            // 0..15
    const int tx = tid & 15;            // 0..15

    float acc[8][8];
#pragma unroll
    for (int i = 0; i < 8; i++)
#pragma unroll
        for (int j = 0; j < 8; j++) acc[i][j] = 0.f;

    for (int k0 = 0; k0 < K; k0 += BKK) {
        float4 av = *(const float4*)(Aptr + k0);
        float4 bv = *(const float4*)(Bptr + k0);
        As[lk4 + 0][lrow] = av.x;  As[lk4 + 1][lrow] = av.y;
        As[lk4 + 2][lrow] = av.z;  As[lk4 + 3][lrow] = av.w;
        Bs[lk4 + 0][lrow] = bv.x;  Bs[lk4 + 1][lrow] = bv.y;
        Bs[lk4 + 2][lrow] = bv.z;  Bs[lk4 + 3][lrow] = bv.w;
        __syncthreads();

#pragma unroll
        for (int kk = 0; kk < BKK; kk++) {
            float ar[8], br[8];
#pragma unroll
            for (int i = 0; i < 4; i++) {
                ar[i]     = As[kk][ty * 4 + i];
                ar[4 + i] = As[kk][64 + ty * 4 + i];
                br[i]     = Bs[kk][tx * 4 + i];
                br[4 + i] = Bs[kk][64 + tx * 4 + i];
            }
#pragma unroll
            for (int i = 0; i < 8; i++)
#pragma unroll
                for (int j = 0; j < 8; j++) acc[i][j] += ar[i] * br[j];
        }
        __syncthreads();
    }

#pragma unroll
    for (int i = 0; i < 8; i++) {
        int row = brow + ((i < 4) ? (ty * 4 + i) : (64 + ty * 4 + i - 4));
        float4* c0 = (float4*)(C + (size_t)row * N + bcol + tx * 4);
        float4* c1 = (float4*)(C + (size_t)row * N + bcol + 64 + tx * 4);
        *c0 = make_float4(acc[i][0], acc[i][1], acc[i][2], acc[i][3]);
        *c1 = make_float4(acc[i][4], acc[i][5], acc[i][6], acc[i][7]);
    }
}

// ------------------- beta / g projections (N=32 skinny GEMM) ----------------
// block: 256 threads, 64 rows per block; cols 0..15 -> W_b, 16..31 -> W_a
__global__ __launch_bounds__(256) void proj_ab(const float* __restrict__ hs,
                                               const float* __restrict__ Wb,
                                               const float* __restrict__ Wa,
                                               const float* __restrict__ dt_bias,
                                               const float* __restrict__ A_log,
                                               float* __restrict__ gout,
                                               float* __restrict__ bout) {
    __shared__ float As[64][32];
    __shared__ float Ws[32][32];
    const int tid = threadIdx.x;
    const int row0 = blockIdx.x * 64;
    const int ty = tid >> 5;     // 0..7
    const int tx = tid & 31;     // 0..31

    float acc[8];
#pragma unroll
    for (int i = 0; i < 8; i++) acc[i] = 0.f;

    const int ar = tid >> 2;           // 0..63
    const int ak = (tid & 3) * 8;      // 0,8,16,24

    for (int k0 = 0; k0 < Hh; k0 += 32) {
        float4 a0 = *(const float4*)(hs + (size_t)(row0 + ar) * Hh + k0 + ak);
        float4 a1 = *(const float4*)(hs + (size_t)(row0 + ar) * Hh + k0 + ak + 4);
        As[ar][ak + 0] = a0.x; As[ar][ak + 1] = a0.y; As[ar][ak + 2] = a0.z; As[ar][ak + 3] = a0.w;
        As[ar][ak + 4] = a1.x; As[ar][ak + 5] = a1.y; As[ar][ak + 6] = a1.z; As[ar][ak + 7] = a1.w;
        // weights: lane-contiguous in k
#pragma unroll
        for (int i = tid; i < 1024; i += 256) {
            int n = i >> 5, kk = i & 31;
            float w = (n < 16) ? Wb[(size_t)n * Hh + k0 + kk]
                               : Wa[(size_t)(n - 16) * Hh + k0 + kk];
            Ws[kk][n] = w;
        }
        __syncthreads();
#pragma unroll
        for (int kk = 0; kk < 32; kk++) {
            float w = Ws[kk][tx];
#pragma unroll
            for (int i = 0; i < 8; i++) acc[i] += As[ty * 8 + i][kk] * w;
        }
        __syncthreads();
    }

    if (tx < 16) {
#pragma unroll
        for (int i = 0; i < 8; i++) {
            int row = row0 + ty * 8 + i;
            bout[(size_t)row * NVH + tx] = 1.f / (1.f + expf(-acc[i]));
        }
    } else {
        int hh = tx - 16;
        float al = expf(A_log[hh]);
        float db = dt_bias[hh];
#pragma unroll
        for (int i = 0; i < 8; i++) {
            int row = row0 + ty * 8 + i;
            float x = acc[i] + db;
            float sp = (x > 20.f) ? x : log1pf(expf(x));
            gout[(size_t)row * NVH + hh] = -al * sp;
        }
    }
}

// ------------------------- depthwise causal conv + silu ---------------------
// x,y: [B,S,CONV_DIM]; w: [CONV_DIM,1,KSZ]. One thread = 4 channels (float4).
__global__ __launch_bounds__(256) void conv_silu(const float* __restrict__ x,
                                                 const float* __restrict__ w,
                                                 float* __restrict__ y) {
    const int C4 = CONV_DIM / 4;   // 512
    int idx = blockIdx.x * blockDim.x + threadIdx.x;   // 0 .. B*S*C4-1
    int c4 = idx & (C4 - 1);
    int s  = (idx >> 9) & (Ss - 1);
    int b  = idx >> 21;

    // taps: channel c -> w[c*4 + j]; load 4 channels' taps
    float4 t0 = ((const float4*)w)[c4 * 4 + 0];
    float4 t1 = ((const float4*)w)[c4 * 4 + 1];
    float4 t2 = ((const float4*)w)[c4 * 4 + 2];
    float4 t3 = ((const float4*)w)[c4 * 4 + 3];

    float a0 = 0.f, a1 = 0.f, a2 = 0.f, a3 = 0.f;
#pragma unroll
    for (int j = 0; j < KSZ; j++) {
        int st = s - (KSZ - 1) + j;
        if (st < 0) continue;
        float4 xv = ((const float4*)x)[((size_t)b * Ss + st) * C4 + c4];
        float w0 = (j == 0) ? t0.x : (j == 1) ? t0.y : (j == 2) ? t0.z : t0.w;
        float w1 = (j == 0) ? t1.x : (j == 1) ? t1.y : (j == 2) ? t1.z : t1.w;
        float w2 = (j == 0) ? t2.x : (j == 1) ? t2.y : (j == 2) ? t2.z : t2.w;
        float w3 = (j == 0) ? t3.x : (j == 1) ? t3.y : (j == 2) ? t3.z : t3.w;
        a0 += w0 * xv.x; a1 += w1 * xv.y; a2 += w2 * xv.z; a3 += w3 * xv.w;
    }
    float4 out;
    out.x = a0 / (1.f + expf(-a0));
    out.y = a1 / (1.f + expf(-a1));
    out.z = a2 / (1.f + expf(-a2));
    out.w = a3 / (1.f + expf(-a3));
    ((float4*)y)[((size_t)b * Ss + s) * C4 + c4] = out;
}

// ------------------------- gated delta-rule recurrence ----------------------
// 32 CTAs (b,h), 256 threads. Thread owns S[k in kb..kb+16, v], v = warp*8+(lane>>2).
#define CH 32
__global__ __launch_bounds__(256) void delta_scan(const float* __restrict__ conv,
                                                  const float* __restrict__ gg,
                                                  const float* __restrict__ bb_,
                                                  float* __restrict__ out) {
    __shared__ float qs[CH][64];
    __shared__ float ks2[CH][64];
    __shared__ float vs2[CH][64];
    __shared__ float ds[CH];
    __shared__ float bs[CH];

    const int tid  = threadIdx.x;
    const int lane = tid & 31;
    const int warp = tid >> 5;
    const int b = blockIdx.x >> 4;
    const int h = blockIdx.x & 15;

    const int v  = warp * 8 + (lane >> 2);
    const int kb = (lane & 3) * 16;

    const int qoff = (h >> 1) * DK;
    const int koff = KEY_DIM + (h >> 1) * DK;
    const int voff = 2 * KEY_DIM + h * DV;

    float S0r[8], S1r[8];
#pragma unroll
    for (int i = 0; i < 8; i++) { S0r[i] = 0.f; S1r[i] = 0.f; }

    for (int chunk = 0; chunk < Ss / CH; chunk++) {
        const int base = chunk * CH;
        // stage CH timesteps of q,k,v
        for (int i = tid; i < CH * 64; i += 256) {
            int t = i >> 6, c = i & 63;
            size_t row = ((size_t)b * Ss + base + t) * CONV_DIM;
            qs[t][c]  = conv[row + qoff + c] * 0.125f;   // DK^-0.5
            ks2[t][c] = conv[row + koff + c];
            vs2[t][c] = conv[row + voff + c];
        }
        if (tid < CH) {
            size_t r = ((size_t)b * Ss + base + tid) * NVH + h;
            ds[tid] = expf(gg[r]);
            bs[tid] = bb_[r];
        }
        __syncthreads();

        for (int t = 0; t < CH; t++) {
            float dec = ds[t];
            float bt  = bs[t];
            float kv0 = 0.f, kv1 = 0.f;
#pragma unroll
            for (int i = 0; i < 8; i++) {
                S0r[i] *= dec;
                S1r[i] *= dec;
                kv0 += S0r[i] * ks2[t][kb + i];
                kv1 += S1r[i] * ks2[t][kb + 8 + i];
            }
            float kv = kv0 + kv1;
            kv += __shfl_xor_sync(0xffffffffu, kv, 1);
            kv += __shfl_xor_sync(0xffffffffu, kv, 2);
            float delta = (vs2[t][v] - kv) * bt;
            float o0 = 0.f, o1 = 0.f;
#pragma unroll
            for (int i = 0; i < 8; i++) {
                S0r[i] += ks2[t][kb + i] * delta;
                S1r[i] += ks2[t][kb + 8 + i] * delta;
                o0 += S0r[i] * qs[t][kb + i];
                o1 += S1r[i] * qs[t][kb + 8 + i];
            }
            float o = o0 + o1;
            o += __shfl_xor_sync(0xffffffffu, o, 1);
            o += __shfl_xor_sync(0xffffffffu, o, 2);
            if ((lane & 3) == 0)
                out[(((size_t)b * Ss + base + t) * NVH + h) * DV + v] = o;
        }
        __syncthreads();
    }
}

// ------------------------- gated RMSNorm ------------------------------------
// one warp per (b,s,h); lane handles v=lane and v=lane+32
__global__ __launch_bounds__(256) void gate_norm(const float* __restrict__ o,
                                                 const float* __restrict__ z,
                                                 const float* __restrict__ w,
                                                 float* __restrict__ hout) {
    int gid  = blockIdx.x * 8 + (threadIdx.x >> 5);  // bsh index
    int lane = threadIdx.x & 31;
    size_t base = (size_t)gid * 64;
    float z0 = z[base + lane],      z1 = z[base + lane + 32];
    float o0 = o[base + lane],      o1 = o[base + lane + 32];
    float v0 = o0 * (z0 / (1.f + expf(-z0)));
    float v1 = o1 * (z1 / (1.f + expf(-z1)));
    float ss = v0 * v0 + v1 * v1;
#pragma unroll
    for (int m = 16; m; m >>= 1) ss += __shfl_xor_sync(0xffffffffu, ss, m);
    float scale = rsqrtf(ss * (1.f / 64.f) + 1e-6f);
    hout[base + lane]      = v0 * scale * w[lane];
    hout[base + lane + 32] = v1 * scale * w[lane + 32];
}

// ------------------------- launcher -----------------------------------------
extern "C" void kernel_launch(void* const* d_in, const int* in_sizes, int n_in,
                              void* d_out, int out_size) {
    const float* hs       = (const float*)d_in[0];
    const float* W_qkv    = (const float*)d_in[1];
    const float* conv_w   = (const float*)d_in[2];
    const float* W_z      = (const float*)d_in[3];
    const float* W_b      = (const float*)d_in[4];
    const float* W_a      = (const float*)d_in[5];
    const float* dt_bias  = (const float*)d_in[6];
    const float* A_log    = (const float*)d_in[7];
    const float* norm_w   = (const float*)d_in[8];
    const float* W_out    = (const float*)d_in[9];
    float* out = (float*)d_out;

    float *p_mixed, *p_conv, *p_z, *p_g, *p_beta, *p_o, *p_h;
    cudaGetSymbolAddress((void**)&p_mixed, g_mixed);
    cudaGetSymbolAddress((void**)&p_conv,  g_conv);
    cudaGetSymbolAddress((void**)&p_z,     g_z);
    cudaGetSymbolAddress((void**)&p_g,     g_g);
    cudaGetSymbolAddress((void**)&p_beta,  g_beta);
    cudaGetSymbolAddress((void**)&p_o,     g_o);
    cudaGetSymbolAddress((void**)&p_h,     g_h);

    // 1) qkv projection: [8192,1024] x [2048,1024]^T
    sgemm_tn<<<dim3(CONV_DIM / BN, MROWS / BM), 256>>>(hs, W_qkv, p_mixed,
                                                       MROWS, CONV_DIM, Hh);
    // 2) z projection
    sgemm_tn<<<dim3(VAL_DIM / BN, MROWS / BM), 256>>>(hs, W_z, p_z,
                                                      MROWS, VAL_DIM, Hh);
    // 3) beta / g projections
    proj_ab<<<MROWS / 64, 256>>>(hs, W_b, W_a, dt_bias, A_log, p_g, p_beta);
    // 4) depthwise conv + silu
    conv_silu<<<(Bb * Ss * (CONV_DIM / 4)) / 256, 256>>>(p_mixed, conv_w, p_conv);
    // 5) gated delta-rule scan
    delta_scan<<<Bb * NVH, 256>>>(p_conv, p_g, p_beta, p_o);
    // 6) gated RMSNorm
    gate_norm<<<(Bb * Ss * NVH) / 8, 256>>>(p_o, p_z, norm_w, p_h);
    // 7) output projection
    sgemm_tn<<<dim3(Hh / BN, MROWS / BM), 256>>>(p_h, W_out, out,
                                                 MROWS, Hh, Hh);
}

// round 4
// speedup vs baseline: 1.4124x; 1.4124x over previous
#include <cuda_runtime.h>
#include <cuda_fp16.h>
#include <cuda_bf16.h>
#include <math.h>
#include <stdint.h>
#include <stddef.h>

// Problem constants
#define Bb 2
#define Ss 4096
#define Hh 1024
#define NKH 8
#define NVH 16
#define DK 64
#define DV 64
#define KEY_DIM 512
#define VAL_DIM 1024
#define CONV_DIM 2048
#define KSZ 4
#define MROWS (Bb*Ss)        // 8192

// ------------------------- scratch (static device memory) -------------------
__device__ float g_mixed[(size_t)Bb*Ss*CONV_DIM];
__device__ float g_conv [(size_t)Bb*Ss*CONV_DIM];
__device__ float g_z    [(size_t)Bb*Ss*VAL_DIM];
__device__ float g_g    [(size_t)Bb*Ss*NVH];
__device__ float g_beta [(size_t)Bb*Ss*NVH];
__device__ float g_o    [(size_t)Bb*Ss*VAL_DIM];
__device__ float g_h    [(size_t)Bb*Ss*VAL_DIM];

// ========================= helpers ==========================================
__device__ __forceinline__ uint32_t smem_u32(const void* p) {
    uint32_t a;
    asm("{ .reg .u64 t; cvta.to.shared.u64 t, %1; cvt.u32.u64 %0, t; }"
        : "=r"(a) : "l"(p));
    return a;
}

#define LDSM4(r0, r1, r2, r3, addr) \
    asm volatile("ldmatrix.sync.aligned.m8n8.x4.shared.b16 {%0,%1,%2,%3}, [%4];" \
                 : "=r"(r0), "=r"(r1), "=r"(r2), "=r"(r3) : "r"(addr))

#define MMA16816(d, a, b0, b1) \
    asm volatile("mma.sync.aligned.m16n8k16.row.col.f32.f16.f16.f32 " \
                 "{%0,%1,%2,%3},{%4,%5,%6,%7},{%8,%9},{%0,%1,%2,%3};" \
                 : "+f"((d)[0]), "+f"((d)[1]), "+f"((d)[2]), "+f"((d)[3]) \
                 : "r"((a)[0]), "r"((a)[1]), "r"((a)[2]), "r"((a)[3]), \
                   "r"(b0), "r"(b1))

// convert 8 floats -> 8 fp16 hi + 8 fp16 lo (packed as uint4 each)
__device__ __forceinline__ void cvt8(const float4& x, const float4& y,
                                     uint4& hi, uint4& lo) {
    __half hx0 = __float2half_rn(x.x), hx1 = __float2half_rn(x.y);
    __half hx2 = __float2half_rn(x.z), hx3 = __float2half_rn(x.w);
    __half hy0 = __float2half_rn(y.x), hy1 = __float2half_rn(y.y);
    __half hy2 = __float2half_rn(y.z), hy3 = __float2half_rn(y.w);
    __half lx0 = __float2half_rn(x.x - __half2float(hx0));
    __half lx1 = __float2half_rn(x.y - __half2float(hx1));
    __half lx2 = __float2half_rn(x.z - __half2float(hx2));
    __half lx3 = __float2half_rn(x.w - __half2float(hx3));
    __half ly0 = __float2half_rn(y.x - __half2float(hy0));
    __half ly1 = __float2half_rn(y.y - __half2float(hy1));
    __half ly2 = __float2half_rn(y.z - __half2float(hy2));
    __half ly3 = __float2half_rn(y.w - __half2float(hy3));
    __half2 p;
    p = __halves2half2(hx0, hx1); hi.x = *(uint32_t*)&p;
    p = __halves2half2(hx2, hx3); hi.y = *(uint32_t*)&p;
    p = __halves2half2(hy0, hy1); hi.z = *(uint32_t*)&p;
    p = __halves2half2(hy2, hy3); hi.w = *(uint32_t*)&p;
    p = __halves2half2(lx0, lx1); lo.x = *(uint32_t*)&p;
    p = __halves2half2(lx2, lx3); lo.y = *(uint32_t*)&p;
    p = __halves2half2(ly0, ly1); lo.z = *(uint32_t*)&p;
    p = __halves2half2(ly2, ly3); lo.w = *(uint32_t*)&p;
}

// ===================== split-fp16 HMMA GEMM: C = A * B^T ====================
// A: [M,K] fp32 row-major, B: [N,K] fp32 row-major, C: [M,N] fp32.
// Tile 128x128xK32, 8 warps of 32x64, double-buffered smem.
// Rows padded to 40 halves (80B) -> conflict-free ldmatrix.
#define ROWP 40
#define ARR_BYTES (128 * ROWP * 2)       // 10240
#define STG_BYTES (4 * ARR_BYTES)        // 40960: Ahi,Alo,Bhi,Blo
#define GEMM_SMEM (2 * STG_BYTES)        // 81920

__global__ __launch_bounds__(256, 1) void hmma_gemm_tn(const float* __restrict__ A,
                                                       const float* __restrict__ B,
                                                       float* __restrict__ C,
                                                       int M, int N, int K) {
    extern __shared__ char dynsmem[];
    const uint32_t sbase = smem_u32(dynsmem);

    const int tid  = threadIdx.x;
    const int lane = tid & 31;
    const int wid  = tid >> 5;
    const int wm   = wid & 3;            // 4 m-groups of 32
    const int wn   = wid >> 2;           // 2 n-groups of 64
    const int brow = blockIdx.y * 128;
    const int bcol = blockIdx.x * 128;

    // global load mapping: thread -> (row = tid>>1, 16 cols at (tid&1)*16)
    const int grow = tid >> 1;
    const int gcol = (tid & 1) * 16;
    const float* Aptr = A + (size_t)(brow + grow) * K + gcol;
    const float* Bptr = B + (size_t)(bcol + grow) * K + gcol;
    // smem store address (bytes within array): row*80 + gcol*2
    const uint32_t stoff = (uint32_t)(grow * ROWP * 2 + gcol * 2);

    // ldmatrix addresses (per-lane, within-array byte offsets)
    const uint32_t aRow  = (uint32_t)(wm * 32 + (lane & 15));
    const uint32_t aKby  = (uint32_t)((lane >> 4) * 16);
    const uint32_t bRow  = (uint32_t)(wn * 64 + (lane & 7) + ((lane >> 4) << 3));
    const uint32_t bKby  = (uint32_t)(((lane >> 3) & 1) * 16);

    float acc[2][8][4];
#pragma unroll
    for (int i = 0; i < 2; i++)
#pragma unroll
        for (int j = 0; j < 8; j++)
#pragma unroll
            for (int c = 0; c < 4; c++) acc[i][j][c] = 0.f;

    const int NK = K / 32;
    float4 ar0, ar1, ar2, ar3, br0, br1, br2, br3;

    // prologue: load stage 0
    ar0 = *(const float4*)(Aptr + 0);  ar1 = *(const float4*)(Aptr + 4);
    ar2 = *(const float4*)(Aptr + 8);  ar3 = *(const float4*)(Aptr + 12);
    br0 = *(const float4*)(Bptr + 0);  br1 = *(const float4*)(Bptr + 4);
    br2 = *(const float4*)(Bptr + 8);  br3 = *(const float4*)(Bptr + 12);
    {
        uint32_t sb = sbase;            // stage 0
        uint4 hi, lo;
        cvt8(ar0, ar1, hi, lo);
        *(uint4*)(dynsmem + (sb - sbase) + 0 * ARR_BYTES + stoff) = hi;
        *(uint4*)(dynsmem + (sb - sbase) + 1 * ARR_BYTES + stoff) = lo;
        cvt8(ar2, ar3, hi, lo);
        *(uint4*)(dynsmem + 0 * ARR_BYTES + stoff + 16) = hi;
        *(uint4*)(dynsmem + 1 * ARR_BYTES + stoff + 16) = lo;
        cvt8(br0, br1, hi, lo);
        *(uint4*)(dynsmem + 2 * ARR_BYTES + stoff) = hi;
        *(uint4*)(dynsmem + 3 * ARR_BYTES + stoff) = lo;
        cvt8(br2, br3, hi, lo);
        *(uint4*)(dynsmem + 2 * ARR_BYTES + stoff + 16) = hi;
        *(uint4*)(dynsmem + 3 * ARR_BYTES + stoff + 16) = lo;
    }

    for (int s = 0; s < NK; s++) {
        __syncthreads();   // stage s&1 visible

        // prefetch next stage into regs
        if (s + 1 < NK) {
            const float* An = Aptr + (s + 1) * 32;
            const float* Bn = Bptr + (s + 1) * 32;
            ar0 = *(const float4*)(An + 0);  ar1 = *(const float4*)(An + 4);
            ar2 = *(const float4*)(An + 8);  ar3 = *(const float4*)(An + 12);
            br0 = *(const float4*)(Bn + 0);  br1 = *(const float4*)(Bn + 4);
            br2 = *(const float4*)(Bn + 8);  br3 = *(const float4*)(Bn + 12);
        }

        // compute on stage s&1
        const uint32_t stg = sbase + (uint32_t)((s & 1) * STG_BYTES);
#pragma unroll
        for (int kh = 0; kh < 2; kh++) {
            const uint32_t kby = (uint32_t)(kh * 32);
            uint32_t ah[2][4], al[2][4], bh[8][2], bl[8][2];
#pragma unroll
            for (int mi = 0; mi < 2; mi++) {
                uint32_t ad = stg + (aRow + mi * 16) * (ROWP * 2) + aKby + kby;
                LDSM4(ah[mi][0], ah[mi][1], ah[mi][2], ah[mi][3], ad);
                LDSM4(al[mi][0], al[mi][1], al[mi][2], al[mi][3], ad + ARR_BYTES);
            }
#pragma unroll
            for (int ng = 0; ng < 4; ng++) {
                uint32_t bd = stg + 2 * ARR_BYTES +
                              (bRow + ng * 16) * (ROWP * 2) + bKby + kby;
                LDSM4(bh[ng*2][0], bh[ng*2][1], bh[ng*2+1][0], bh[ng*2+1][1], bd);
                LDSM4(bl[ng*2][0], bl[ng*2][1], bl[ng*2+1][0], bl[ng*2+1][1],
                      bd + ARR_BYTES);
            }
#pragma unroll
            for (int mi = 0; mi < 2; mi++)
#pragma unroll
                for (int nf = 0; nf < 8; nf++) {
                    MMA16816(acc[mi][nf], ah[mi], bh[nf][0], bh[nf][1]);
                    MMA16816(acc[mi][nf], ah[mi], bl[nf][0], bl[nf][1]);
                    MMA16816(acc[mi][nf], al[mi], bh[nf][0], bh[nf][1]);
                }
        }

        // store next stage
        if (s + 1 < NK) {
            __syncthreads();   // everyone done reading the buffer we overwrite
            char* nb = dynsmem + ((s + 1) & 1) * STG_BYTES;
            uint4 hi, lo;
            cvt8(ar0, ar1, hi, lo);
            *(uint4*)(nb + 0 * ARR_BYTES + stoff) = hi;
            *(uint4*)(nb + 1 * ARR_BYTES + stoff) = lo;
            cvt8(ar2, ar3, hi, lo);
            *(uint4*)(nb + 0 * ARR_BYTES + stoff + 16) = hi;
            *(uint4*)(nb + 1 * ARR_BYTES + stoff + 16) = lo;
            cvt8(br0, br1, hi, lo);
            *(uint4*)(nb + 2 * ARR_BYTES + stoff) = hi;
            *(uint4*)(nb + 3 * ARR_BYTES + stoff) = lo;
            cvt8(br2, br3, hi, lo);
            *(uint4*)(nb + 2 * ARR_BYTES + stoff + 16) = hi;
            *(uint4*)(nb + 3 * ARR_BYTES + stoff + 16) = lo;
        }
    }

    // epilogue: write accumulators
#pragma unroll
    for (int mi = 0; mi < 2; mi++) {
        int r0 = brow + wm * 32 + mi * 16 + (lane >> 2);
#pragma unroll
        for (int nf = 0; nf < 8; nf++) {
            int c = bcol + wn * 64 + nf * 8 + (lane & 3) * 2;
            *(float2*)&C[(size_t)r0 * N + c] =
                make_float2(acc[mi][nf][0], acc[mi][nf][1]);
            *(float2*)&C[(size_t)(r0 + 8) * N + c] =
                make_float2(acc[mi][nf][2], acc[mi][nf][3]);
        }
    }
}

// ------------------- beta / g projections (N=32 skinny GEMM) ----------------
__global__ __launch_bounds__(256) void proj_ab(const float* __restrict__ hs,
                                               const float* __restrict__ Wb,
                                               const float* __restrict__ Wa,
                                               const float* __restrict__ dt_bias,
                                               const float* __restrict__ A_log,
                                               float* __restrict__ gout,
                                               float* __restrict__ bout) {
    __shared__ float As[64][32];
    __shared__ float Ws[32][32];
    const int tid = threadIdx.x;
    const int row0 = blockIdx.x * 64;
    const int ty = tid >> 5;
    const int tx = tid & 31;

    float acc[8];
#pragma unroll
    for (int i = 0; i < 8; i++) acc[i] = 0.f;

    const int ar = tid >> 2;
    const int ak = (tid & 3) * 8;

    for (int k0 = 0; k0 < Hh; k0 += 32) {
        float4 a0 = *(const float4*)(hs + (size_t)(row0 + ar) * Hh + k0 + ak);
        float4 a1 = *(const float4*)(hs + (size_t)(row0 + ar) * Hh + k0 + ak + 4);
        As[ar][ak + 0] = a0.x; As[ar][ak + 1] = a0.y; As[ar][ak + 2] = a0.z; As[ar][ak + 3] = a0.w;
        As[ar][ak + 4] = a1.x; As[ar][ak + 5] = a1.y; As[ar][ak + 6] = a1.z; As[ar][ak + 7] = a1.w;
#pragma unroll
        for (int i = tid; i < 1024; i += 256) {
            int n = i >> 5, kk = i & 31;
            float w = (n < 16) ? Wb[(size_t)n * Hh + k0 + kk]
                               : Wa[(size_t)(n - 16) * Hh + k0 + kk];
            Ws[kk][n] = w;
        }
        __syncthreads();
#pragma unroll
        for (int kk = 0; kk < 32; kk++) {
            float w = Ws[kk][tx];
#pragma unroll
            for (int i = 0; i < 8; i++) acc[i] += As[ty * 8 + i][kk] * w;
        }
        __syncthreads();
    }

    if (tx < 16) {
#pragma unroll
        for (int i = 0; i < 8; i++) {
            int row = row0 + ty * 8 + i;
            bout[(size_t)row * NVH + tx] = 1.f / (1.f + expf(-acc[i]));
        }
    } else {
        int hh = tx - 16;
        float al = expf(A_log[hh]);
        float db = dt_bias[hh];
#pragma unroll
        for (int i = 0; i < 8; i++) {
            int row = row0 + ty * 8 + i;
            float x = acc[i] + db;
            float sp = (x > 20.f) ? x : log1pf(expf(x));
            gout[(size_t)row * NVH + hh] = -al * sp;
        }
    }
}

// ------------------------- depthwise causal conv + silu ---------------------
__global__ __launch_bounds__(256) void conv_silu(const float* __restrict__ x,
                                                 const float* __restrict__ w,
                                                 float* __restrict__ y) {
    const int C4 = CONV_DIM / 4;
    int idx = blockIdx.x * blockDim.x + threadIdx.x;
    int c4 = idx & (C4 - 1);
    int s  = (idx >> 9) & (Ss - 1);
    int b  = idx >> 21;

    float4 t0 = ((const float4*)w)[c4 * 4 + 0];
    float4 t1 = ((const float4*)w)[c4 * 4 + 1];
    float4 t2 = ((const float4*)w)[c4 * 4 + 2];
    float4 t3 = ((const float4*)w)[c4 * 4 + 3];

    float a0 = 0.f, a1 = 0.f, a2 = 0.f, a3 = 0.f;
#pragma unroll
    for (int j = 0; j < KSZ; j++) {
        int st = s - (KSZ - 1) + j;
        if (st < 0) continue;
        float4 xv = ((const float4*)x)[((size_t)b * Ss + st) * C4 + c4];
        float w0 = (j == 0) ? t0.x : (j == 1) ? t0.y : (j == 2) ? t0.z : t0.w;
        float w1 = (j == 0) ? t1.x : (j == 1) ? t1.y : (j == 2) ? t1.z : t1.w;
        float w2 = (j == 0) ? t2.x : (j == 1) ? t2.y : (j == 2) ? t2.z : t2.w;
        float w3 = (j == 0) ? t3.x : (j == 1) ? t3.y : (j == 2) ? t3.z : t3.w;
        a0 += w0 * xv.x; a1 += w1 * xv.y; a2 += w2 * xv.z; a3 += w3 * xv.w;
    }
    float4 out;
    out.x = a0 / (1.f + expf(-a0));
    out.y = a1 / (1.f + expf(-a1));
    out.z = a2 / (1.f + expf(-a2));
    out.w = a3 / (1.f + expf(-a3));
    ((float4*)y)[((size_t)b * Ss + s) * C4 + c4] = out;
}

// ------------------------- gated delta-rule recurrence ----------------------
#define CHNK 32
__global__ __launch_bounds__(256) void delta_scan(const float* __restrict__ conv,
                                                  const float* __restrict__ gg,
                                                  const float* __restrict__ bb_,
                                                  float* __restrict__ out) {
    __shared__ float qs[CHNK][64];
    __shared__ float ks2[CHNK][64];
    __shared__ float vs2[CHNK][64];
    __shared__ float ds[CHNK];
    __shared__ float bs[CHNK];

    const int tid  = threadIdx.x;
    const int lane = tid & 31;
    const int warp = tid >> 5;
    const int b = blockIdx.x >> 4;
    const int h = blockIdx.x & 15;

    const int v  = warp * 8 + (lane >> 2);
    const int kb = (lane & 3) * 16;

    const int qoff = (h >> 1) * DK;
    const int koff = KEY_DIM + (h >> 1) * DK;
    const int voff = 2 * KEY_DIM + h * DV;

    float S0r[8], S1r[8];
#pragma unroll
    for (int i = 0; i < 8; i++) { S0r[i] = 0.f; S1r[i] = 0.f; }

    for (int chunk = 0; chunk < Ss / CHNK; chunk++) {
        const int base = chunk * CHNK;
        for (int i = tid; i < CHNK * 64; i += 256) {
            int t = i >> 6, c = i & 63;
            size_t row = ((size_t)b * Ss + base + t) * CONV_DIM;
            qs[t][c]  = conv[row + qoff + c] * 0.125f;
            ks2[t][c] = conv[row + koff + c];
            vs2[t][c] = conv[row + voff + c];
        }
        if (tid < CHNK) {
            size_t r = ((size_t)b * Ss + base + tid) * NVH + h;
            ds[tid] = expf(gg[r]);
            bs[tid] = bb_[r];
        }
        __syncthreads();

        for (int t = 0; t < CHNK; t++) {
            float dec = ds[t];
            float bt  = bs[t];
            float kv0 = 0.f, kv1 = 0.f;
#pragma unroll
            for (int i = 0; i < 8; i++) {
                S0r[i] *= dec;
                S1r[i] *= dec;
                kv0 += S0r[i] * ks2[t][kb + i];
                kv1 += S1r[i] * ks2[t][kb + 8 + i];
            }
            float kv = kv0 + kv1;
            kv += __shfl_xor_sync(0xffffffffu, kv, 1);
            kv += __shfl_xor_sync(0xffffffffu, kv, 2);
            float delta = (vs2[t][v] - kv) * bt;
            float o0 = 0.f, o1 = 0.f;
#pragma unroll
            for (int i = 0; i < 8; i++) {
                S0r[i] += ks2[t][kb + i] * delta;
                S1r[i] += ks2[t][kb + 8 + i] * delta;
                o0 += S0r[i] * qs[t][kb + i];
                o1 += S1r[i] * qs[t][kb + 8 + i];
            }
            float o = o0 + o1;
            o += __shfl_xor_sync(0xffffffffu, o, 1);
            o += __shfl_xor_sync(0xffffffffu, o, 2);
            if ((lane & 3) == 0)
                out[(((size_t)b * Ss + base + t) * NVH + h) * DV + v] = o;
        }
        __syncthreads();
    }
}

// ------------------------- gated RMSNorm ------------------------------------
__global__ __launch_bounds__(256) void gate_norm(const float* __restrict__ o,
                                                 const float* __restrict__ z,
                                                 const float* __restrict__ w,
                                                 float* __restrict__ hout) {
    int gid  = blockIdx.x * 8 + (threadIdx.x >> 5);
    int lane = threadIdx.x & 31;
    size_t base = (size_t)gid * 64;
    float z0 = z[base + lane],      z1 = z[base + lane + 32];
    float o0 = o[base + lane],      o1 = o[base + lane + 32];
    float v0 = o0 * (z0 / (1.f + expf(-z0)));
    float v1 = o1 * (z1 / (1.f + expf(-z1)));
    float ss = v0 * v0 + v1 * v1;
#pragma unroll
    for (int m = 16; m; m >>= 1) ss += __shfl_xor_sync(0xffffffffu, ss, m);
    float scale = rsqrtf(ss * (1.f / 64.f) + 1e-6f);
    hout[base + lane]      = v0 * scale * w[lane];
    hout[base + lane + 32] = v1 * scale * w[lane + 32];
}

// ------------------------- launcher -----------------------------------------
extern "C" void kernel_launch(void* const* d_in, const int* in_sizes, int n_in,
                              void* d_out, int out_size) {
    const float* hs       = (const float*)d_in[0];
    const float* W_qkv    = (const float*)d_in[1];
    const float* conv_w   = (const float*)d_in[2];
    const float* W_z      = (const float*)d_in[3];
    const float* W_b      = (const float*)d_in[4];
    const float* W_a      = (const float*)d_in[5];
    const float* dt_bias  = (const float*)d_in[6];
    const float* A_log    = (const float*)d_in[7];
    const float* norm_w   = (const float*)d_in[8];
    const float* W_out    = (const float*)d_in[9];
    float* out = (float*)d_out;

    float *p_mixed, *p_conv, *p_z, *p_g, *p_beta, *p_o, *p_h;
    cudaGetSymbolAddress((void**)&p_mixed, g_mixed);
    cudaGetSymbolAddress((void**)&p_conv,  g_conv);
    cudaGetSymbolAddress((void**)&p_z,     g_z);
    cudaGetSymbolAddress((void**)&p_g,     g_g);
    cudaGetSymbolAddress((void**)&p_beta,  g_beta);
    cudaGetSymbolAddress((void**)&p_o,     g_o);
    cudaGetSymbolAddress((void**)&p_h,     g_h);

    cudaFuncSetAttribute(hmma_gemm_tn, cudaFuncAttributeMaxDynamicSharedMemorySize,
                         GEMM_SMEM);

    // 1) qkv projection: [8192,1024] x [2048,1024]^T
    hmma_gemm_tn<<<dim3(CONV_DIM / 128, MROWS / 128), 256, GEMM_SMEM>>>(
        hs, W_qkv, p_mixed, MROWS, CONV_DIM, Hh);
    // 2) z projection
    hmma_gemm_tn<<<dim3(VAL_DIM / 128, MROWS / 128), 256, GEMM_SMEM>>>(
        hs, W_z, p_z, MROWS, VAL_DIM, Hh);
    // 3) beta / g projections
    proj_ab<<<MROWS / 64, 256>>>(hs, W_b, W_a, dt_bias, A_log, p_g, p_beta);
    // 4) depthwise conv + silu
    conv_silu<<<(Bb * Ss * (CONV_DIM / 4)) / 256, 256>>>(p_mixed, conv_w, p_conv);
    // 5) gated delta-rule scan
    delta_scan<<<Bb * NVH, 256>>>(p_conv, p_g, p_beta, p_o);
    // 6) gated RMSNorm
    gate_norm<<<(Bb * Ss * NVH) / 8, 256>>>(p_o, p_z, norm_w, p_h);
    // 7) output projection
    hmma_gemm_tn<<<dim3(Hh / 128, MROWS / 128), 256, GEMM_SMEM>>>(
        p_h, W_out, out, MROWS, Hh, Hh);
}